// round 3
// baseline (speedup 1.0000x reference)
#include <cuda_runtime.h>
#include <cuda_bf16.h>
#include <math_constants.h>

#define N_NODES 10000
#define N_EDGES 320000
#define HID 256
#define HEADS 8
#define HDIM 32
#define MAXE 512   // per-(node,head) smem edge cache; fallback recompute beyond

// ---------------- scratch (no allocation allowed) ----------------
__device__ float g_h[N_NODES * HID];     // transformed features of current layer
__device__ float g_feat[N_NODES * HID];  // layer-2 input (elu(out1))
__device__ float g_as[N_NODES * HEADS];
__device__ float g_ad[N_NODES * HEADS];
__device__ int   g_deg[N_NODES];
__device__ int   g_fill[N_NODES];
__device__ int   g_off[N_NODES + 1];
__device__ int   g_srt[N_EDGES];         // src node id, grouped by dst (CSR)
__device__ int   g_is64;                 // 1 if edges buffer is int64, 0 if int32

// ---------------- edge dtype detection ----------------
// If the buffer is int64 (LE, values < 2^31), every odd int32 word is 0.
// If it is int32 (random node ids 0..9999), odd words are ~never all zero.
__global__ void detect_kernel(const int* __restrict__ e32) {
    int allz = 1;
    #pragma unroll
    for (int i = 1; i < 64; i += 2)
        if (e32[i] != 0) { allz = 0; break; }
    g_is64 = allz;
}

__device__ __forceinline__ int edge_at(const void* edges, int idx) {
    if (g_is64) return (int)((const long long*)edges)[idx];
    return ((const int*)edges)[idx];
}

// ---------------- CSR build ----------------
__global__ void zero_kernel() {
    int i = blockIdx.x * blockDim.x + threadIdx.x;
    if (i < N_NODES) { g_deg[i] = 0; g_fill[i] = 0; }
}

__global__ void hist_kernel(const void* __restrict__ edges) {
    int e = blockIdx.x * blockDim.x + threadIdx.x;
    if (e < N_EDGES) {
        int dst = edge_at(edges, N_EDGES + e);
        if ((unsigned)dst < (unsigned)N_NODES)
            atomicAdd(&g_deg[dst], 1);
    }
}

__global__ void scan_kernel() {   // single block, 1024 threads
    __shared__ int sb[1024];
    __shared__ int carry;
    int t = threadIdx.x;
    if (t == 0) { carry = 0; g_off[0] = 0; }
    __syncthreads();
    for (int base = 0; base < N_NODES; base += 1024) {
        int i = base + t;
        int v = (i < N_NODES) ? g_deg[i] : 0;
        sb[t] = v;
        __syncthreads();
        #pragma unroll
        for (int o = 1; o < 1024; o <<= 1) {
            int add = (t >= o) ? sb[t - o] : 0;
            __syncthreads();
            sb[t] += add;
            __syncthreads();
        }
        if (i < N_NODES) g_off[i + 1] = sb[t] + carry;
        __syncthreads();
        if (t == 1023) carry += sb[1023];
        __syncthreads();
    }
}

__global__ void fill_kernel(const void* __restrict__ edges) {
    int e = blockIdx.x * blockDim.x + threadIdx.x;
    if (e < N_EDGES) {
        int src = edge_at(edges, e);
        int dst = edge_at(edges, N_EDGES + e);
        if ((unsigned)src < (unsigned)N_NODES && (unsigned)dst < (unsigned)N_NODES) {
            int pos = g_off[dst] + atomicAdd(&g_fill[dst], 1);
            if ((unsigned)pos < (unsigned)N_EDGES) g_srt[pos] = src;
        }
    }
}

// ---------------- GEMM: h = feat @ W, fused alpha_src/alpha_dst ----------------
// Block: 256 threads, computes 32 node rows x all 256 output cols.
// Thread t owns column t. Warp w == head w (cols 32w..32w+31).
// layer2 != 0 -> input is g_feat (device global), else kernel arg x.
__global__ __launch_bounds__(256) void gemm_alpha_kernel(
    const float* __restrict__ x, int layer2, const float* __restrict__ W,
    const float* __restrict__ a_s, const float* __restrict__ a_d)
{
    const float* feat = layer2 ? (const float*)g_feat : x;

    __shared__ float sf[32][33];  // feat tile [node][k], padded
    int t = threadIdx.x;
    int n0 = blockIdx.x * 32;

    float acc[32];
    #pragma unroll
    for (int i = 0; i < 32; i++) acc[i] = 0.f;

    for (int k0 = 0; k0 < HID; k0 += 32) {
        // load 32x32 feat tile (coalesced in k)
        #pragma unroll
        for (int i = t; i < 32 * 32; i += 256) {
            int nn = i >> 5, kk = i & 31;
            int node = n0 + nn;
            sf[nn][kk] = (node < N_NODES) ? feat[node * HID + k0 + kk] : 0.f;
        }
        __syncthreads();
        #pragma unroll
        for (int kk = 0; kk < 32; kk++) {
            float w = W[(k0 + kk) * HID + t];
            #pragma unroll
            for (int nn = 0; nn < 32; nn++)
                acc[nn] += sf[nn][kk] * w;
        }
        __syncthreads();
    }

    int hd = t >> 5, ch = t & 31;
    float asv = a_s[hd * HDIM + ch];
    float adv = a_d[hd * HDIM + ch];

    #pragma unroll 4
    for (int nn = 0; nn < 32; nn++) {
        int node = n0 + nn;
        if (node >= N_NODES) break;   // uniform across block
        float v = acc[nn];
        g_h[node * HID + t] = v;
        float ps = v * asv;
        float pd = v * adv;
        #pragma unroll
        for (int o = 16; o > 0; o >>= 1) {
            ps += __shfl_down_sync(0xffffffffu, ps, o);
            pd += __shfl_down_sync(0xffffffffu, pd, o);
        }
        if (ch == 0) {
            g_as[node * HEADS + hd] = ps;
            g_ad[node * HEADS + hd] = pd;
        }
    }
}

// ---------------- Aggregation: softmax over incoming edges + weighted sum ---------
// Grid: N_NODES blocks x 256 threads. Warp = head, lane = channel.
// mode=1: out = elu(agg + b) -> g_feat ; mode=0: out = agg + b -> d_out
__global__ __launch_bounds__(256) void agg_kernel(
    const float* __restrict__ b, float* __restrict__ out, int mode)
{
    __shared__ float se[HEADS][MAXE];  // per-head e / w cache
    __shared__ int   ss[HEADS][MAXE];  // per-head src cache

    int n    = blockIdx.x;
    int hd   = threadIdx.x >> 5;
    int lane = threadIdx.x & 31;

    int beg = g_off[n];
    int deg = g_off[n + 1] - beg;
    float adv = g_ad[n * HEADS + hd];

    // Phase 1: leaky-relu'd attention logits + running max (lanes parallel over edges)
    float m = -CUDART_INF_F;
    for (int j = lane; j < deg; j += 32) {
        int s = g_srt[beg + j];
        float e = g_as[s * HEADS + hd] + adv;
        e = (e > 0.f) ? e : 0.2f * e;
        if (j < MAXE) { se[hd][j] = e; ss[hd][j] = s; }
        m = fmaxf(m, e);
    }
    #pragma unroll
    for (int o = 16; o > 0; o >>= 1)
        m = fmaxf(m, __shfl_xor_sync(0xffffffffu, m, o));
    __syncwarp();

    // Phase 1.5: w = exp(e - m), computed once per edge; denominator reduce
    float sum = 0.f;
    for (int j = lane; j < deg; j += 32) {
        float e;
        if (j < MAXE) e = se[hd][j];
        else {
            int s = g_srt[beg + j];
            e = g_as[s * HEADS + hd] + adv;
            e = (e > 0.f) ? e : 0.2f * e;
        }
        float w = __expf(e - m);
        if (j < MAXE) se[hd][j] = w;
        sum += w;
    }
    #pragma unroll
    for (int o = 16; o > 0; o >>= 1)
        sum += __shfl_xor_sync(0xffffffffu, sum, o);
    __syncwarp();

    // Phase 2: serial over edges, coalesced 128B gathers of h[src][hd][:]
    float acc = 0.f;
    #pragma unroll 4
    for (int j = 0; j < deg; j++) {
        int s; float w;
        if (j < MAXE) { s = ss[hd][j]; w = se[hd][j]; }
        else {
            s = g_srt[beg + j];
            float e = g_as[s * HEADS + hd] + adv;
            e = (e > 0.f) ? e : 0.2f * e;
            w = __expf(e - m);
        }
        acc += g_h[s * HID + hd * HDIM + lane] * w;
    }

    float o = acc / (sum + 1e-16f) + b[hd * HDIM + lane];
    if (mode == 1) {
        o = (o > 0.f) ? o : (__expf(o) - 1.f);
        g_feat[n * HID + threadIdx.x] = o;
    } else {
        out[n * HID + threadIdx.x] = o;
    }
}

// ---------------- launch ----------------
extern "C" void kernel_launch(void* const* d_in, const int* in_sizes, int n_in,
                              void* d_out, int out_size)
{
    const float* x     = (const float*)d_in[0];
    const void*  edges = d_in[1];                 // int32 or int64 — detected on device
    const float* W1    = (const float*)d_in[2];
    const float* as1   = (const float*)d_in[3];
    const float* ad1   = (const float*)d_in[4];
    const float* b1    = (const float*)d_in[5];
    const float* W2    = (const float*)d_in[6];
    const float* as2   = (const float*)d_in[7];
    const float* ad2   = (const float*)d_in[8];
    const float* b2    = (const float*)d_in[9];
    float* out = (float*)d_out;

    // CSR build (identical every call — deterministic)
    detect_kernel<<<1, 1>>>((const int*)edges);
    zero_kernel<<<(N_NODES + 255) / 256, 256>>>();
    hist_kernel<<<(N_EDGES + 255) / 256, 256>>>(edges);
    scan_kernel<<<1, 1024>>>();
    fill_kernel<<<(N_EDGES + 255) / 256, 256>>>(edges);

    int gemm_blocks = (N_NODES + 31) / 32;

    // Layer 1
    gemm_alpha_kernel<<<gemm_blocks, 256>>>(x, 0, W1, as1, ad1);
    agg_kernel<<<N_NODES, 256>>>(b1, out, /*mode=*/1);

    // Layer 2
    gemm_alpha_kernel<<<gemm_blocks, 256>>>(x, 1, W2, as2, ad2);
    agg_kernel<<<N_NODES, 256>>>(b2, out, /*mode=*/0);
}

// round 4
// speedup vs baseline: 1.3385x; 1.3385x over previous
#include <cuda_runtime.h>
#include <cuda_bf16.h>
#include <math_constants.h>

#define N_NODES 10000
#define N_EDGES 320000
#define HID 256
#define HEADS 8
#define HDIM 32
#define MAXE 128   // per-(node,head) smem edge cache; fallback recompute beyond

// ---------------- scratch (no allocation allowed) ----------------
__device__ float g_h[N_NODES * HID];     // transformed features of current layer
__device__ float g_feat[N_NODES * HID];  // layer-2 input (elu(out1))
__device__ float g_as[N_NODES * HEADS];
__device__ float g_ad[N_NODES * HEADS];
__device__ int   g_deg[N_NODES];
__device__ int   g_fill[N_NODES];
__device__ int   g_off[N_NODES + 1];
__device__ int   g_srt[N_EDGES];         // src node id, grouped by dst (CSR)
__device__ int   g_is64;                 // 1 if edges buffer is int64, 0 if int32

// ---------------- edge dtype detection ----------------
__global__ void detect_kernel(const int* __restrict__ e32) {
    int allz = 1;
    #pragma unroll
    for (int i = 1; i < 64; i += 2)
        if (e32[i] != 0) { allz = 0; break; }
    g_is64 = allz;
}

__device__ __forceinline__ int edge_at(const void* edges, int idx) {
    if (g_is64) return (int)((const long long*)edges)[idx];
    return ((const int*)edges)[idx];
}

// ---------------- CSR build ----------------
__global__ void zero_kernel() {
    int i = blockIdx.x * blockDim.x + threadIdx.x;
    if (i < N_NODES) { g_deg[i] = 0; g_fill[i] = 0; }
}

__global__ void hist_kernel(const void* __restrict__ edges) {
    int e = blockIdx.x * blockDim.x + threadIdx.x;
    if (e < N_EDGES) {
        int dst = edge_at(edges, N_EDGES + e);
        if ((unsigned)dst < (unsigned)N_NODES)
            atomicAdd(&g_deg[dst], 1);
    }
}

// Two-level warp-shuffle scan: thread t serially scans a 10-element chunk,
// then 1024 chunk-sums are scanned with shuffles. One block, ~3us.
__global__ __launch_bounds__(1024) void scan_kernel() {
    __shared__ int warp_tot[32];
    const int PER = 10;                 // 1024*10 = 10240 >= N_NODES
    int t    = threadIdx.x;
    int lane = t & 31, wid = t >> 5;
    int base = t * PER;

    int v[PER]; int s = 0;
    #pragma unroll
    for (int i = 0; i < PER; i++) {
        int idx = base + i;
        int d = (idx < N_NODES) ? g_deg[idx] : 0;
        v[i] = s; s += d;               // v[i] = exclusive prefix within chunk
    }
    // inclusive scan of chunk sums across 1024 threads
    int x = s;
    #pragma unroll
    for (int o = 1; o < 32; o <<= 1) {
        int y = __shfl_up_sync(0xffffffffu, x, o);
        if (lane >= o) x += y;
    }
    if (lane == 31) warp_tot[wid] = x;
    __syncthreads();
    if (wid == 0) {
        int y = warp_tot[lane];
        #pragma unroll
        for (int o = 1; o < 32; o <<= 1) {
            int z = __shfl_up_sync(0xffffffffu, y, o);
            if (lane >= o) y += z;
        }
        warp_tot[lane] = y;
    }
    __syncthreads();
    int excl = x - s + (wid > 0 ? warp_tot[wid - 1] : 0);
    #pragma unroll
    for (int i = 0; i < PER; i++) {
        int idx = base + i;
        if (idx < N_NODES) g_off[idx] = excl + v[i];
    }
    if (t == 1023) g_off[N_NODES] = excl + s;
}

__global__ void fill_kernel(const void* __restrict__ edges) {
    int e = blockIdx.x * blockDim.x + threadIdx.x;
    if (e < N_EDGES) {
        int src = edge_at(edges, e);
        int dst = edge_at(edges, N_EDGES + e);
        if ((unsigned)src < (unsigned)N_NODES && (unsigned)dst < (unsigned)N_NODES) {
            int pos = g_off[dst] + atomicAdd(&g_fill[dst], 1);
            if ((unsigned)pos < (unsigned)N_EDGES) g_srt[pos] = src;
        }
    }
}

// ---------------- GEMM: h = feat @ W, fused alpha_src/alpha_dst ----------------
// Block: 256 threads -> tile of 32 nodes x 256 cols.
// Thread: 8 nodes x 4 consecutive cols (32 accumulators, float4 everywhere).
//   r  = t>>6        (node sub-group, 8 nodes)
//   c4 = (t&63)*4    (first of 4 consecutive cols)
// Inner loop per k: 1 float4 LDS (W) + 2 float4 LDS (feat) + 32 FFMA.
__global__ __launch_bounds__(256) void gemm_alpha_kernel(
    const float* __restrict__ x, int layer2, const float* __restrict__ W,
    const float* __restrict__ a_s, const float* __restrict__ a_d)
{
    const float* feat = layer2 ? (const float*)g_feat : x;

    __shared__ float sW[32 * 256];    // W tile  [kk][col], 32 KB
    __shared__ float sf[32][36];      // feat tile TRANSPOSED [kk][node], padded

    int t  = threadIdx.x;
    int n0 = blockIdx.x * 32;
    int r  = t >> 6;
    int c4 = (t & 63) * 4;

    float4 acc[8];
    #pragma unroll
    for (int i = 0; i < 8; i++) acc[i] = make_float4(0.f, 0.f, 0.f, 0.f);

    for (int k0 = 0; k0 < HID; k0 += 32) {
        // stage W[k0:k0+32][0:256] -> sW (float4, fully coalesced)
        const float4* Wv = (const float4*)W;
        float4*       sWv = (float4*)sW;
        #pragma unroll
        for (int q = 0; q < 8; q++) {
            int vidx = t + 256 * q;                 // 2048 float4s
            sWv[vidx] = Wv[k0 * 64 + vidx];
        }
        // stage feat tile transposed: sf[kk][nn] = feat[n0+nn][k0+kk]
        #pragma unroll
        for (int p = 0; p < 4; p++) {
            int i = t + 256 * p;                    // 1024 elements
            int nn = i >> 5, kk = i & 31;
            int node = n0 + nn;
            sf[kk][nn] = (node < N_NODES) ? feat[node * HID + k0 + kk] : 0.f;
        }
        __syncthreads();

        #pragma unroll
        for (int kk = 0; kk < 32; kk++) {
            float4 wv = *(const float4*)&sW[kk * 256 + c4];
            float4 a0 = *(const float4*)&sf[kk][r * 8];
            float4 a1 = *(const float4*)&sf[kk][r * 8 + 4];
            float av[8] = {a0.x, a0.y, a0.z, a0.w, a1.x, a1.y, a1.z, a1.w};
            #pragma unroll
            for (int i = 0; i < 8; i++) {
                acc[i].x = fmaf(av[i], wv.x, acc[i].x);
                acc[i].y = fmaf(av[i], wv.y, acc[i].y);
                acc[i].z = fmaf(av[i], wv.z, acc[i].z);
                acc[i].w = fmaf(av[i], wv.w, acc[i].w);
            }
        }
        __syncthreads();
    }

    // epilogue: store h (float4) + alpha_src/alpha_dst partial dots
    int lane = t & 31;
    int whalf = (t >> 5) & 1;                 // which 128-col half this warp owns
    int head  = whalf * 4 + (lane >> 3);      // global head of this thread's 4 cols
    float4 as4 = ((const float4*)a_s)[whalf * 32 + lane];
    float4 ad4 = ((const float4*)a_d)[whalf * 32 + lane];

    #pragma unroll
    for (int i = 0; i < 8; i++) {
        int node = n0 + r * 8 + i;
        if (node >= N_NODES) break;           // uniform across warp (r uniform)
        float4 v = acc[i];
        ((float4*)g_h)[node * 64 + whalf * 32 + lane] = v;
        float ps = v.x * as4.x + v.y * as4.y + v.z * as4.z + v.w * as4.w;
        float pd = v.x * ad4.x + v.y * ad4.y + v.z * ad4.z + v.w * ad4.w;
        #pragma unroll
        for (int o = 4; o > 0; o >>= 1) {     // reduce within 8-lane head groups
            ps += __shfl_down_sync(0xffffffffu, ps, o, 8);
            pd += __shfl_down_sync(0xffffffffu, pd, o, 8);
        }
        if ((lane & 7) == 0) {
            g_as[node * HEADS + head] = ps;
            g_ad[node * HEADS + head] = pd;
        }
    }
}

// ---------------- Aggregation: softmax over incoming edges + weighted sum ---------
// Grid: N_NODES blocks x 256 threads. Warp = head, lane = channel.
// mode=1: out = elu(agg + b) -> g_feat ; mode=0: out = agg + b -> d_out
__global__ __launch_bounds__(256) void agg_kernel(
    const float* __restrict__ b, float* __restrict__ out, int mode)
{
    __shared__ float se[HEADS][MAXE];  // per-head e / w cache
    __shared__ int   ss[HEADS][MAXE];  // per-head src cache

    int n    = blockIdx.x;
    int hd   = threadIdx.x >> 5;
    int lane = threadIdx.x & 31;

    int beg = g_off[n];
    int deg = g_off[n + 1] - beg;
    float adv = g_ad[n * HEADS + hd];

    // Phase 1: leaky-relu'd attention logits + running max (lanes parallel over edges)
    float m = -CUDART_INF_F;
    for (int j = lane; j < deg; j += 32) {
        int s = g_srt[beg + j];
        float e = g_as[s * HEADS + hd] + adv;
        e = (e > 0.f) ? e : 0.2f * e;
        if (j < MAXE) { se[hd][j] = e; ss[hd][j] = s; }
        m = fmaxf(m, e);
    }
    #pragma unroll
    for (int o = 16; o > 0; o >>= 1)
        m = fmaxf(m, __shfl_xor_sync(0xffffffffu, m, o));
    __syncwarp();

    // Phase 1.5: w = exp(e - m), computed once per edge; denominator reduce
    float sum = 0.f;
    for (int j = lane; j < deg; j += 32) {
        float e;
        if (j < MAXE) e = se[hd][j];
        else {
            int s = g_srt[beg + j];
            e = g_as[s * HEADS + hd] + adv;
            e = (e > 0.f) ? e : 0.2f * e;
        }
        float w = __expf(e - m);
        if (j < MAXE) se[hd][j] = w;
        sum += w;
    }
    #pragma unroll
    for (int o = 16; o > 0; o >>= 1)
        sum += __shfl_xor_sync(0xffffffffu, sum, o);
    __syncwarp();

    // Phase 2: serial over edges, coalesced 128B gathers of h[src][hd][:]
    float acc = 0.f;
    #pragma unroll 4
    for (int j = 0; j < deg; j++) {
        int s; float w;
        if (j < MAXE) { s = ss[hd][j]; w = se[hd][j]; }
        else {
            s = g_srt[beg + j];
            float e = g_as[s * HEADS + hd] + adv;
            e = (e > 0.f) ? e : 0.2f * e;
            w = __expf(e - m);
        }
        acc += g_h[s * HID + hd * HDIM + lane] * w;
    }

    float o = acc / (sum + 1e-16f) + b[hd * HDIM + lane];
    if (mode == 1) {
        o = (o > 0.f) ? o : (__expf(o) - 1.f);
        g_feat[n * HID + threadIdx.x] = o;
    } else {
        out[n * HID + threadIdx.x] = o;
    }
}

// ---------------- launch ----------------
extern "C" void kernel_launch(void* const* d_in, const int* in_sizes, int n_in,
                              void* d_out, int out_size)
{
    const float* x     = (const float*)d_in[0];
    const void*  edges = d_in[1];                 // int32 or int64 — detected on device
    const float* W1    = (const float*)d_in[2];
    const float* as1   = (const float*)d_in[3];
    const float* ad1   = (const float*)d_in[4];
    const float* b1    = (const float*)d_in[5];
    const float* W2    = (const float*)d_in[6];
    const float* as2   = (const float*)d_in[7];
    const float* ad2   = (const float*)d_in[8];
    const float* b2    = (const float*)d_in[9];
    float* out = (float*)d_out;

    // CSR build (identical every call — deterministic)
    detect_kernel<<<1, 1>>>((const int*)edges);
    zero_kernel<<<(N_NODES + 255) / 256, 256>>>();
    hist_kernel<<<(N_EDGES + 255) / 256, 256>>>(edges);
    scan_kernel<<<1, 1024>>>();
    fill_kernel<<<(N_EDGES + 255) / 256, 256>>>(edges);

    int gemm_blocks = (N_NODES + 31) / 32;   // 313

    // Layer 1
    gemm_alpha_kernel<<<gemm_blocks, 256>>>(x, 0, W1, as1, ad1);
    agg_kernel<<<N_NODES, 256>>>(b1, out, /*mode=*/1);

    // Layer 2
    gemm_alpha_kernel<<<gemm_blocks, 256>>>(x, 1, W2, as2, ad2);
    agg_kernel<<<N_NODES, 256>>>(b2, out, /*mode=*/0);
}